// round 1
// baseline (speedup 1.0000x reference)
#include <cuda_runtime.h>
#include <math.h>

// Problem constants
#define N_TOK 2048
#define C_DIM 1024
#define E_NUM 32
#define TOPK  4
#define H_RT  512
#define HS_SH 1024
#define NPAIR (N_TOK * TOPK)   // 8192 (token, expert-slot) pairs

// ---------------------------------------------------------------------------
// Scratch (static __device__ arrays: allocation-free per harness rules)
// ---------------------------------------------------------------------------
__device__ float d_u_sh[N_TOK * 2 * HS_SH];   // 2048 x 2048  shared gate-proj out
__device__ float d_hs  [N_TOK * HS_SH];       // 2048 x 1024  shared swiglu hidden
__device__ float d_u_rt[NPAIR * 2 * H_RT];    // 8192 x 1024  routed gate-proj out
__device__ float d_h_rt[NPAIR * H_RT];        // 8192 x 512   routed swiglu hidden
__device__ int   d_cnt [E_NUM];               // tokens per expert
__device__ int   d_slot[E_NUM * N_TOK];       // per-expert slot list (slot = n*4+k)
__device__ float d_wt  [NPAIR];               // routing weight per slot

__global__ void zero_cnt_kernel() {
    if (threadIdx.x < E_NUM) d_cnt[threadIdx.x] = 0;
}

// ---------------------------------------------------------------------------
// Gating: scores = sigmoid(x @ gate_w), top-4 (with bias for selection only),
// normalized weights, and per-expert slot-list assignment.
// One block (32 threads = one warp, one expert per lane) per token.
// ---------------------------------------------------------------------------
__global__ void gate_kernel(const float* __restrict__ x,
                            const float* __restrict__ gw,
                            const float* __restrict__ gb) {
    int n = blockIdx.x;
    int e = threadIdx.x;                       // 0..31
    const float* xr = x + n * C_DIM;
    float acc = 0.f;
#pragma unroll 8
    for (int c = 0; c < C_DIM; c++)
        acc = fmaf(xr[c], gw[c * E_NUM + e], acc);
    float s = 1.f / (1.f + expf(-acc));

    __shared__ float sc[E_NUM];
    sc[e] = s;
    __syncwarp();

    if (e == 0) {
        float sb[E_NUM];
#pragma unroll
        for (int i = 0; i < E_NUM; i++) sb[i] = sc[i] + gb[i];
        int   idx[TOPK];
        float wsum = 0.f;
#pragma unroll
        for (int k = 0; k < TOPK; k++) {
            int best = 0; float bv = -1e30f;
            for (int i = 0; i < E_NUM; i++)
                if (sb[i] > bv) { bv = sb[i]; best = i; }
            sb[best] = -2e30f;                 // remove; top_k prefers lower index on ties
            idx[k] = best;
            wsum += sc[best];
        }
        float inv = 1.f / wsum;                // ROUTE_SCALE = 1
#pragma unroll
        for (int k = 0; k < TOPK; k++) {
            int ee = idx[k];
            d_wt[n * TOPK + k] = sc[ee] * inv;
            int pos = atomicAdd(&d_cnt[ee], 1);
            d_slot[ee * N_TOK + pos] = n * TOPK + k;
        }
    }
}

// ---------------------------------------------------------------------------
// Dense fp32 SGEMM: C[M,N] = A[M,K] @ B[K,N]; all dims multiples of 64.
// 64x64 tile, BK=16, 256 threads, 4x4 per-thread microtile.
// ---------------------------------------------------------------------------
__global__ void __launch_bounds__(256) sgemm_plain(const float* __restrict__ A,
                                                   const float* __restrict__ B,
                                                   float* __restrict__ Cd,
                                                   int N, int K) {
    __shared__ float As[16][68];   // row stride 68 floats (272B, 16B aligned)
    __shared__ float Bs[16][64];
    int t  = threadIdx.x;
    int m0 = blockIdx.x * 64, n0 = blockIdx.y * 64;
    int ar = t >> 2,  ak = (t & 3)  << 2;   // A loader: row, k-offset
    int br = t >> 4,  bc = (t & 15) << 2;   // B loader
    int tm = (t >> 4) << 2, tn = (t & 15) << 2;

    const float* Ap = A + (m0 + ar) * K;
    const float* Bp = B + n0;
    float acc[4][4] = {};

    for (int k0 = 0; k0 < K; k0 += 16) {
        float4 av = *(const float4*)(Ap + k0 + ak);
        As[ak + 0][ar] = av.x; As[ak + 1][ar] = av.y;
        As[ak + 2][ar] = av.z; As[ak + 3][ar] = av.w;
        *(float4*)&Bs[br][bc] = *(const float4*)(Bp + (k0 + br) * N + bc);
        __syncthreads();
#pragma unroll
        for (int kk = 0; kk < 16; kk++) {
            float4 a4 = *(const float4*)&As[kk][tm];
            float4 b4 = *(const float4*)&Bs[kk][tn];
            float aa[4] = {a4.x, a4.y, a4.z, a4.w};
            float bb[4] = {b4.x, b4.y, b4.z, b4.w};
#pragma unroll
            for (int i = 0; i < 4; i++)
#pragma unroll
                for (int j = 0; j < 4; j++)
                    acc[i][j] = fmaf(aa[i], bb[j], acc[i][j]);
        }
        __syncthreads();
    }
#pragma unroll
    for (int i = 0; i < 4; i++) {
        float4 v = make_float4(acc[i][0], acc[i][1], acc[i][2], acc[i][3]);
        *(float4*)&Cd[(m0 + tm + i) * N + n0 + tn] = v;
    }
}

// ---------------------------------------------------------------------------
// Grouped routed SGEMM. blockIdx.z = expert.
//   DOWN=false: A rows = x[token] (K=1024), B = expert_gate_w[e] (1024x1024),
//               store rows to d_u_rt[slot].
//   DOWN=true : A rows = d_h_rt[slot] (K=512), B = expert_down_w[e] (512x1024),
//               atomicAdd wt[slot]*row into out[token].
// N = 1024 in both phases.
// ---------------------------------------------------------------------------
template <bool DOWN>
__global__ void __launch_bounds__(256) sgemm_routed(const float* __restrict__ x,
                                                    const float* __restrict__ W,
                                                    float* __restrict__ out) {
    int e   = blockIdx.z;
    int cnt = d_cnt[e];
    int m0  = blockIdx.x * 64;
    if (m0 >= cnt) return;

    const int K = DOWN ? H_RT : C_DIM;
    const int N = 1024;

    __shared__ float As[16][68];
    __shared__ float Bs[16][64];
    __shared__ int   s_slot[64];

    int t = threadIdx.x;
    if (t < 64) {
        int m = m0 + t;
        s_slot[t] = (m < cnt) ? d_slot[e * N_TOK + m] : -1;
    }
    __syncthreads();

    int n0 = blockIdx.y * 64;
    int ar = t >> 2,  ak = (t & 3)  << 2;
    int br = t >> 4,  bc = (t & 15) << 2;
    int tm = (t >> 4) << 2, tn = (t & 15) << 2;

    int  slotA = s_slot[ar];
    bool aval  = slotA >= 0;
    const float* Ap;
    if (DOWN) Ap = d_h_rt + (long)(aval ? slotA : 0) * H_RT;
    else      Ap = x      + (long)(aval ? (slotA >> 2) : 0) * C_DIM;
    const float* Bp = W + (long)e * K * N + n0;

    float acc[4][4] = {};
    for (int k0 = 0; k0 < K; k0 += 16) {
        float4 av = aval ? *(const float4*)(Ap + k0 + ak)
                         : make_float4(0.f, 0.f, 0.f, 0.f);
        As[ak + 0][ar] = av.x; As[ak + 1][ar] = av.y;
        As[ak + 2][ar] = av.z; As[ak + 3][ar] = av.w;
        *(float4*)&Bs[br][bc] = *(const float4*)(Bp + (k0 + br) * N + bc);
        __syncthreads();
#pragma unroll
        for (int kk = 0; kk < 16; kk++) {
            float4 a4 = *(const float4*)&As[kk][tm];
            float4 b4 = *(const float4*)&Bs[kk][tn];
            float aa[4] = {a4.x, a4.y, a4.z, a4.w};
            float bb[4] = {b4.x, b4.y, b4.z, b4.w};
#pragma unroll
            for (int i = 0; i < 4; i++)
#pragma unroll
                for (int j = 0; j < 4; j++)
                    acc[i][j] = fmaf(aa[i], bb[j], acc[i][j]);
        }
        __syncthreads();
    }

#pragma unroll
    for (int i = 0; i < 4; i++) {
        int m = m0 + tm + i;
        if (m >= cnt) break;
        int slot = s_slot[tm + i];
        if (!DOWN) {
            float4 v = make_float4(acc[i][0], acc[i][1], acc[i][2], acc[i][3]);
            *(float4*)&d_u_rt[(long)slot * 1024 + n0 + tn] = v;
        } else {
            int   token = slot >> 2;
            float w     = d_wt[slot];
            float* op   = out + (long)token * C_DIM + n0 + tn;
            atomicAdd(op + 0, w * acc[i][0]);
            atomicAdd(op + 1, w * acc[i][1]);
            atomicAdd(op + 2, w * acc[i][2]);
            atomicAdd(op + 3, w * acc[i][3]);
        }
    }
}

// ---------------------------------------------------------------------------
// SwiGLU elementwise: u = [y | g], h = silu(g) * y
// ---------------------------------------------------------------------------
__global__ void swiglu_sh_kernel() {
    int i = blockIdx.x * 256 + threadIdx.x;           // N_TOK*HS = 2M
    int row = i >> 10, col = i & 1023;
    float y = d_u_sh[row * 2048 + col];
    float g = d_u_sh[row * 2048 + 1024 + col];
    d_hs[i] = y * g / (1.f + expf(-g));
}

__global__ void swiglu_rt_kernel() {
    int i = blockIdx.x * 256 + threadIdx.x;           // NPAIR*H = 4M
    int row = i >> 9, col = i & 511;
    float y = d_u_rt[row * 1024 + col];
    float g = d_u_rt[row * 1024 + 512 + col];
    d_h_rt[i] = y * g / (1.f + expf(-g));
}

// ---------------------------------------------------------------------------
// Launch
// ---------------------------------------------------------------------------
extern "C" void kernel_launch(void* const* d_in, const int* in_sizes, int n_in,
                              void* d_out, int out_size) {
    const float* x     = (const float*)d_in[0];
    const float* gw    = (const float*)d_in[1];
    const float* gb    = (const float*)d_in[2];
    const float* sh_gw = (const float*)d_in[3];
    const float* sh_dw = (const float*)d_in[4];
    const float* ex_gw = (const float*)d_in[5];
    const float* ex_dw = (const float*)d_in[6];
    float* out = (float*)d_out;

    void *p_u_sh, *p_hs;
    cudaGetSymbolAddress(&p_u_sh, d_u_sh);
    cudaGetSymbolAddress(&p_hs,   d_hs);

    zero_cnt_kernel<<<1, 32>>>();
    gate_kernel<<<N_TOK, 32>>>(x, gw, gb);

    // shared expert: u_sh = x @ shared_gate_w  (2048x2048, K=1024)
    sgemm_plain<<<dim3(N_TOK / 64, 2 * HS_SH / 64), 256>>>(x, sh_gw, (float*)p_u_sh,
                                                           2 * HS_SH, C_DIM);
    swiglu_sh_kernel<<<(N_TOK * HS_SH) / 256, 256>>>();
    // out = hs @ shared_down_w  (2048x1024, K=1024)  -- initializes d_out
    sgemm_plain<<<dim3(N_TOK / 64, C_DIM / 64), 256>>>((const float*)p_hs, sh_dw, out,
                                                       C_DIM, HS_SH);

    // routed experts (grouped, gathered via slot lists)
    sgemm_routed<false><<<dim3(N_TOK / 64, 1024 / 64, E_NUM), 256>>>(x, ex_gw, out);
    swiglu_rt_kernel<<<(NPAIR * H_RT) / 256, 256>>>();
    sgemm_routed<true><<<dim3(N_TOK / 64, 1024 / 64, E_NUM), 256>>>(x, ex_dw, out);
}

// round 4
// speedup vs baseline: 1.4514x; 1.4514x over previous
#include <cuda_runtime.h>
#include <cuda_bf16.h>
#include <math.h>
#include <stdint.h>

#define N_TOK 2048
#define C_DIM 1024
#define E_NUM 32
#define TOPK  4
#define H_RT  512
#define HS_SH 1024
#define NPAIR (N_TOK * TOPK)   // 8192

// ---------------------------------------------------------------------------
// Baseline-ISA helpers (no sm_103a-only instructions: ptxas target is sm_103)
// ---------------------------------------------------------------------------
__device__ __forceinline__ uint32_t smem_to_u32(const void* p) {
    uint32_t a;
    asm("{ .reg .u64 t; cvta.to.shared.u64 t, %1; cvt.u32.u64 %0, t; }" : "=r"(a) : "l"(p));
    return a;
}
__device__ __forceinline__ void cp_async16(uint32_t smem_dst, const void* gsrc) {
    asm volatile("cp.async.cg.shared.global [%0], [%1], 16;"
                 :: "r"(smem_dst), "l"(gsrc) : "memory");
}
__device__ __forceinline__ void cp_commit() {
    asm volatile("cp.async.commit_group;" ::: "memory");
}
template <int N>
__device__ __forceinline__ void cp_wait() {
    asm volatile("cp.async.wait_group %0;" :: "n"(N) : "memory");
}
__device__ __forceinline__ void ldsm_x4(uint32_t& r0, uint32_t& r1, uint32_t& r2,
                                        uint32_t& r3, uint32_t addr) {
    asm volatile("ldmatrix.sync.aligned.m8n8.x4.shared.b16 {%0,%1,%2,%3}, [%4];"
                 : "=r"(r0), "=r"(r1), "=r"(r2), "=r"(r3) : "r"(addr));
}
__device__ __forceinline__ void mma16816(float* c, const uint32_t* a, const uint32_t* b) {
    asm volatile("mma.sync.aligned.m16n8k16.row.col.f32.bf16.bf16.f32 "
                 "{%0,%1,%2,%3}, {%4,%5,%6,%7}, {%8,%9}, {%0,%1,%2,%3};"
                 : "+f"(c[0]), "+f"(c[1]), "+f"(c[2]), "+f"(c[3])
                 : "r"(a[0]), "r"(a[1]), "r"(a[2]), "r"(a[3]), "r"(b[0]), "r"(b[1]));
}

// ---------------------------------------------------------------------------
// Scratch
// ---------------------------------------------------------------------------
__device__ __nv_bfloat16 g_x_hi [N_TOK * C_DIM];
__device__ __nv_bfloat16 g_x_lo [N_TOK * C_DIM];
__device__ float         g_u_sh [N_TOK * 2 * HS_SH];
__device__ __nv_bfloat16 g_hs_hi[N_TOK * HS_SH];
__device__ __nv_bfloat16 g_hs_lo[N_TOK * HS_SH];
__device__ float         g_u_rt [NPAIR * 2 * H_RT];
__device__ __nv_bfloat16 g_h_hi [NPAIR * H_RT];
__device__ __nv_bfloat16 g_h_lo [NPAIR * H_RT];
__device__ float         g_y_rt [NPAIR * C_DIM];
__device__ __nv_bfloat16 g_sgw_hi[2 * HS_SH * C_DIM];
__device__ __nv_bfloat16 g_sgw_lo[2 * HS_SH * C_DIM];
__device__ __nv_bfloat16 g_sdw_hi[C_DIM * HS_SH];
__device__ __nv_bfloat16 g_sdw_lo[C_DIM * HS_SH];
__device__ __nv_bfloat16 g_egw_hi[E_NUM * 2 * H_RT * C_DIM];
__device__ __nv_bfloat16 g_egw_lo[E_NUM * 2 * H_RT * C_DIM];
__device__ __nv_bfloat16 g_edw_hi[E_NUM * C_DIM * H_RT];
__device__ __nv_bfloat16 g_edw_lo[E_NUM * C_DIM * H_RT];
__device__ int   d_cnt [E_NUM];
__device__ int   d_slot[E_NUM * N_TOK];
__device__ float d_wt  [NPAIR];

__global__ void zero_cnt_kernel() {
    if (threadIdx.x < E_NUM) d_cnt[threadIdx.x] = 0;
}

// ---------------------------------------------------------------------------
// Gating (verified correct in R1)
// ---------------------------------------------------------------------------
__global__ void gate_kernel(const float* __restrict__ x,
                            const float* __restrict__ gw,
                            const float* __restrict__ gb) {
    int n = blockIdx.x;
    int e = threadIdx.x;
    const float* xr = x + n * C_DIM;
    float acc = 0.f;
#pragma unroll 8
    for (int c = 0; c < C_DIM; c++)
        acc = fmaf(xr[c], gw[c * E_NUM + e], acc);
    float s = 1.f / (1.f + expf(-acc));
    __shared__ float sc[E_NUM];
    sc[e] = s;
    __syncwarp();
    if (e == 0) {
        float sb[E_NUM];
#pragma unroll
        for (int i = 0; i < E_NUM; i++) sb[i] = sc[i] + gb[i];
        int idx[TOPK];
        float wsum = 0.f;
#pragma unroll
        for (int k = 0; k < TOPK; k++) {
            int best = 0; float bv = -1e30f;
            for (int i = 0; i < E_NUM; i++)
                if (sb[i] > bv) { bv = sb[i]; best = i; }
            sb[best] = -2e30f;
            idx[k] = best;
            wsum += sc[best];
        }
        float inv = 1.f / wsum;
#pragma unroll
        for (int k = 0; k < TOPK; k++) {
            int ee = idx[k];
            d_wt[n * TOPK + k] = sc[ee] * inv;
            int pos = atomicAdd(&d_cnt[ee], 1);
            d_slot[ee * N_TOK + pos] = n * TOPK + k;
        }
    }
}

// ---------------------------------------------------------------------------
// fp32 -> bf16 hi/lo split of x
// ---------------------------------------------------------------------------
__global__ void convert_x_kernel(const float* __restrict__ x) {
    int i = blockIdx.x * 256 + threadIdx.x;
    float v = x[i];
    __nv_bfloat16 h = __float2bfloat16_rn(v);
    g_x_hi[i] = h;
    g_x_lo[i] = __float2bfloat16_rn(v - __bfloat162float(h));
}

// ---------------------------------------------------------------------------
// Transpose + hi/lo convert: W[KD,ND] fp32 (batched over z) -> Wt[ND,KD] bf16
// ---------------------------------------------------------------------------
template <int KD, int ND>
__global__ void transpose_convert(const float* __restrict__ W,
                                  __nv_bfloat16* __restrict__ hi,
                                  __nv_bfloat16* __restrict__ lo) {
    int b = blockIdx.z;
    const float* Wb = W + (size_t)b * KD * ND;
    __nv_bfloat16* hb = hi + (size_t)b * KD * ND;
    __nv_bfloat16* lb = lo + (size_t)b * KD * ND;
    __shared__ float ts[32][33];
    int n0 = blockIdx.x * 32, k0 = blockIdx.y * 32;
    int tx = threadIdx.x, ty = threadIdx.y;
#pragma unroll
    for (int j = 0; j < 4; j++)
        ts[ty + 8 * j][tx] = Wb[(size_t)(k0 + ty + 8 * j) * ND + n0 + tx];
    __syncthreads();
#pragma unroll
    for (int j = 0; j < 4; j++) {
        int n = n0 + ty + 8 * j;
        float v = ts[tx][ty + 8 * j];
        __nv_bfloat16 h = __float2bfloat16_rn(v);
        hb[(size_t)n * KD + k0 + tx] = h;
        lb[(size_t)n * KD + k0 + tx] = __float2bfloat16_rn(v - __bfloat162float(h));
    }
}

// ---------------------------------------------------------------------------
// bf16x3 GEMM via mma.sync.m16n8k16.
//   C[M, LDC] (fp32) = (Ahi+Alo)[M,K] @ (Bhi+Blo)[N,K]^T
// 3-phase K loop: (hi,hi), (hi,lo), (lo,hi).
// Block tile 128x128, BK=32, 8 warps (2M x 4N), 64x32 per warp.
// smem rows padded to 40 bf16 (80B) -> conflict-free ldmatrix.
// GATHER: A rows / C rows via per-expert slot lists (blockIdx.z = expert).
// ---------------------------------------------------------------------------
#define PADK 40

template <int K_DIM, int LDC, int ASHIFT, bool GATHER>
__global__ void __launch_bounds__(256) mma_gemm(
    const __nv_bfloat16* __restrict__ Ahi, const __nv_bfloat16* __restrict__ Alo,
    const __nv_bfloat16* __restrict__ Bhi, const __nv_bfloat16* __restrict__ Blo,
    float* __restrict__ C)
{
    __shared__ __align__(16) __nv_bfloat16 sA[2][128 * PADK];
    __shared__ __align__(16) __nv_bfloat16 sB[2][128 * PADK];
    __shared__ int slots[128];

    const int CPP = K_DIM / 32;        // chunks per phase
    const int NC  = 3 * CPP;           // total k-chunks

    int t    = threadIdx.x;
    int wid  = t >> 5, lane = t & 31;
    int e    = GATHER ? blockIdx.z : 0;
    int cnt  = GATHER ? d_cnt[e] : (1 << 30);
    int m0   = blockIdx.x * 128;
    if (GATHER && m0 >= cnt) return;
    int n0   = blockIdx.y * 128;

    if (GATHER && t < 128) {
        int m = m0 + t;
        slots[t] = (m < cnt) ? d_slot[e * N_TOK + m] : 0;
    }
    __syncthreads();

    // --- loader thread geometry: 2 A chunks + 2 B chunks per thread/stage
    int lr0 = t >> 2;              // rows lr0 and lr0+64
    int lc  = (t & 3) * 8;         // k element offset of 16B chunk
    int ga0 = GATHER ? (slots[lr0]      >> ASHIFT) : (m0 + lr0);
    int ga1 = GATHER ? (slots[lr0 + 64] >> ASHIFT) : (m0 + lr0 + 64);
    long aoff0 = (long)ga0 * K_DIM + lc;
    long aoff1 = (long)ga1 * K_DIM + lc;
    long bbase = (long)e * LDC * K_DIM;
    long boff0 = bbase + (long)(n0 + lr0)      * K_DIM + lc;
    long boff1 = bbase + (long)(n0 + lr0 + 64) * K_DIM + lc;

    uint32_t sA0 = smem_to_u32(&sA[0][0]), sA1 = smem_to_u32(&sA[1][0]);
    uint32_t sB0 = smem_to_u32(&sB[0][0]), sB1 = smem_to_u32(&sB[1][0]);
    uint32_t da0 = (uint32_t)(lr0 * PADK + lc) * 2;
    uint32_t da1 = (uint32_t)((lr0 + 64) * PADK + lc) * 2;

    // --- mma thread geometry
    int wm = (wid >> 2) * 64;          // warp M origin (0 or 64)
    int wn = (wid & 3) * 32;           // warp N origin
    float acc[4][4][4];
#pragma unroll
    for (int i = 0; i < 4; i++)
#pragma unroll
        for (int j = 0; j < 4; j++)
#pragma unroll
            for (int r = 0; r < 4; r++) acc[i][j][r] = 0.f;

    // ldmatrix addresses (row within block tile, chunk within BK)
    int lrow = lane & 15;
    int lsel = lane >> 4;              // k-half selector

    auto issue = [&](int ch, int buf) {
        int phase = ch / CPP;
        long koff = (long)(ch - phase * CPP) * 32;
        const __nv_bfloat16* As = (phase < 2) ? Ahi : Alo;
        const __nv_bfloat16* Bs = (phase == 1) ? Blo : Bhi;
        uint32_t ab = buf ? sA1 : sA0;
        uint32_t bb = buf ? sB1 : sB0;
        cp_async16(ab + da0, As + aoff0 + koff);
        cp_async16(ab + da1, As + aoff1 + koff);
        cp_async16(bb + da0, Bs + boff0 + koff);
        cp_async16(bb + da1, Bs + boff1 + koff);
    };

    issue(0, 0);
    cp_commit();

    for (int ch = 0; ch < NC; ch++) {
        int cur = ch & 1;
        if (ch + 1 < NC) {
            issue(ch + 1, cur ^ 1);
            cp_commit();
            cp_wait<1>();
        } else {
            cp_wait<0>();
        }
        __syncthreads();

        uint32_t ab = cur ? sA1 : sA0;
        uint32_t bb = cur ? sB1 : sB0;
#pragma unroll
        for (int s = 0; s < 2; s++) {
            uint32_t a[4][4], b[4][2];
            int kc = s * 2 + lsel;     // 16B chunk index within row
#pragma unroll
            for (int mi = 0; mi < 4; mi++) {
                uint32_t addr = ab + (uint32_t)((wm + mi * 16 + lrow) * PADK + kc * 8) * 2;
                ldsm_x4(a[mi][0], a[mi][1], a[mi][2], a[mi][3], addr);
            }
#pragma unroll
            for (int p = 0; p < 2; p++) {
                uint32_t r0, r1, r2, r3;
                uint32_t addr = bb + (uint32_t)((wn + p * 16 + lrow) * PADK + kc * 8) * 2;
                ldsm_x4(r0, r1, r2, r3, addr);
                b[p * 2 + 0][0] = r0; b[p * 2 + 1][0] = r1;
                b[p * 2 + 0][1] = r2; b[p * 2 + 1][1] = r3;
            }
#pragma unroll
            for (int mi = 0; mi < 4; mi++)
#pragma unroll
                for (int ni = 0; ni < 4; ni++)
                    mma16816(acc[mi][ni], a[mi], b[ni]);
        }
        __syncthreads();
    }

    // --- epilogue: fp32 stores
    int erow = lane >> 2;
    int ecol = (lane & 3) * 2;
#pragma unroll
    for (int mi = 0; mi < 4; mi++) {
#pragma unroll
        for (int half = 0; half < 2; half++) {
            int r = wm + mi * 16 + erow + half * 8;
            bool ok = GATHER ? (m0 + r < cnt) : true;
            if (!ok) continue;
            long crow = GATHER ? slots[r] : (m0 + r);
            float* dst = C + crow * LDC + n0 + wn + ecol;
#pragma unroll
            for (int ni = 0; ni < 4; ni++) {
                float2 v = make_float2(acc[mi][ni][half * 2 + 0],
                                       acc[mi][ni][half * 2 + 1]);
                *(float2*)(dst + ni * 8) = v;
            }
        }
    }
}

// ---------------------------------------------------------------------------
// SwiGLU + hi/lo split
// ---------------------------------------------------------------------------
__global__ void swiglu_sh_kernel() {
    int i = blockIdx.x * 256 + threadIdx.x;
    int row = i >> 10, col = i & 1023;
    float y = g_u_sh[row * 2048 + col];
    float g = g_u_sh[row * 2048 + 1024 + col];
    float h = y * g / (1.f + expf(-g));
    __nv_bfloat16 hh = __float2bfloat16_rn(h);
    g_hs_hi[i] = hh;
    g_hs_lo[i] = __float2bfloat16_rn(h - __bfloat162float(hh));
}
__global__ void swiglu_rt_kernel() {
    int i = blockIdx.x * 256 + threadIdx.x;
    int row = i >> 9, col = i & 511;
    float y = g_u_rt[row * 1024 + col];
    float g = g_u_rt[row * 1024 + 512 + col];
    float h = y * g / (1.f + expf(-g));
    __nv_bfloat16 hh = __float2bfloat16_rn(h);
    g_h_hi[i] = hh;
    g_h_lo[i] = __float2bfloat16_rn(h - __bfloat162float(hh));
}

// ---------------------------------------------------------------------------
// Combine: out[n,:] += sum_k wt[n*4+k] * y_rt[n*4+k,:]
// ---------------------------------------------------------------------------
__global__ void combine_kernel(float* __restrict__ out) {
    int i = blockIdx.x * 256 + threadIdx.x;
    int n = i >> 8, j = i & 255;
    float4 acc = *(float4*)(out + (size_t)n * C_DIM + j * 4);
#pragma unroll
    for (int k = 0; k < TOPK; k++) {
        int slot = n * TOPK + k;
        float w = d_wt[slot];
        float4 v = *(const float4*)(g_y_rt + (size_t)slot * C_DIM + j * 4);
        acc.x += w * v.x; acc.y += w * v.y; acc.z += w * v.z; acc.w += w * v.w;
    }
    *(float4*)(out + (size_t)n * C_DIM + j * 4) = acc;
}

// ---------------------------------------------------------------------------
// Launch
// ---------------------------------------------------------------------------
extern "C" void kernel_launch(void* const* d_in, const int* in_sizes, int n_in,
                              void* d_out, int out_size) {
    const float* x     = (const float*)d_in[0];
    const float* gw    = (const float*)d_in[1];
    const float* gb    = (const float*)d_in[2];
    const float* sh_gw = (const float*)d_in[3];
    const float* sh_dw = (const float*)d_in[4];
    const float* ex_gw = (const float*)d_in[5];
    const float* ex_dw = (const float*)d_in[6];
    float* out = (float*)d_out;

    void *p_xh, *p_xl, *p_hsh, *p_hsl, *p_ush, *p_urt, *p_hh, *p_hl, *p_yrt;
    void *p_sgh, *p_sgl, *p_sdh, *p_sdl, *p_egh, *p_egl, *p_edh, *p_edl;
    cudaGetSymbolAddress(&p_xh, g_x_hi);   cudaGetSymbolAddress(&p_xl, g_x_lo);
    cudaGetSymbolAddress(&p_hsh, g_hs_hi); cudaGetSymbolAddress(&p_hsl, g_hs_lo);
    cudaGetSymbolAddress(&p_ush, g_u_sh);  cudaGetSymbolAddress(&p_urt, g_u_rt);
    cudaGetSymbolAddress(&p_hh, g_h_hi);   cudaGetSymbolAddress(&p_hl, g_h_lo);
    cudaGetSymbolAddress(&p_yrt, g_y_rt);
    cudaGetSymbolAddress(&p_sgh, g_sgw_hi); cudaGetSymbolAddress(&p_sgl, g_sgw_lo);
    cudaGetSymbolAddress(&p_sdh, g_sdw_hi); cudaGetSymbolAddress(&p_sdl, g_sdw_lo);
    cudaGetSymbolAddress(&p_egh, g_egw_hi); cudaGetSymbolAddress(&p_egl, g_egw_lo);
    cudaGetSymbolAddress(&p_edh, g_edw_hi); cudaGetSymbolAddress(&p_edl, g_edw_lo);

    zero_cnt_kernel<<<1, 32>>>();
    gate_kernel<<<N_TOK, 32>>>(x, gw, gb);
    convert_x_kernel<<<(N_TOK * C_DIM) / 256, 256>>>(x);

    dim3 tb(32, 8);
    transpose_convert<1024, 2048><<<dim3(2048 / 32, 1024 / 32, 1), tb>>>(
        sh_gw, (__nv_bfloat16*)p_sgh, (__nv_bfloat16*)p_sgl);
    transpose_convert<1024, 1024><<<dim3(1024 / 32, 1024 / 32, 1), tb>>>(
        sh_dw, (__nv_bfloat16*)p_sdh, (__nv_bfloat16*)p_sdl);
    transpose_convert<1024, 1024><<<dim3(1024 / 32, 1024 / 32, E_NUM), tb>>>(
        ex_gw, (__nv_bfloat16*)p_egh, (__nv_bfloat16*)p_egl);
    transpose_convert<512, 1024><<<dim3(1024 / 32, 512 / 32, E_NUM), tb>>>(
        ex_dw, (__nv_bfloat16*)p_edh, (__nv_bfloat16*)p_edl);

    // shared expert
    mma_gemm<1024, 2048, 0, false><<<dim3(16, 16, 1), 256>>>(
        (const __nv_bfloat16*)p_xh, (const __nv_bfloat16*)p_xl,
        (const __nv_bfloat16*)p_sgh, (const __nv_bfloat16*)p_sgl, (float*)p_ush);
    swiglu_sh_kernel<<<(N_TOK * HS_SH) / 256, 256>>>();
    mma_gemm<1024, 1024, 0, false><<<dim3(16, 8, 1), 256>>>(
        (const __nv_bfloat16*)p_hsh, (const __nv_bfloat16*)p_hsl,
        (const __nv_bfloat16*)p_sdh, (const __nv_bfloat16*)p_sdl, out);

    // routed experts
    mma_gemm<1024, 1024, 2, true><<<dim3(16, 8, E_NUM), 256>>>(
        (const __nv_bfloat16*)p_xh, (const __nv_bfloat16*)p_xl,
        (const __nv_bfloat16*)p_egh, (const __nv_bfloat16*)p_egl, (float*)p_urt);
    swiglu_rt_kernel<<<(NPAIR * H_RT) / 256, 256>>>();
    mma_gemm<512, 1024, 0, true><<<dim3(16, 8, E_NUM), 256>>>(
        (const __nv_bfloat16*)p_hh, (const __nv_bfloat16*)p_hl,
        (const __nv_bfloat16*)p_edh, (const __nv_bfloat16*)p_edl, (float*)p_yrt);
    combine_kernel<<<(N_TOK * 256) / 256, 256>>>(out);
}